// round 12
// baseline (speedup 1.0000x reference)
#include <cuda_runtime.h>
#include <cuda_bf16.h>
#include <math_constants.h>
#include <cstdint>

// Problem dims
#define BB 8
#define SS 2048      // S1 == S2
#define KD 512       // K1_DIM == K2_DIM
#define PKD 256
#define CATD 768     // KD + PKD
#define AD 512       // ATT_DIM
#define DV 512

// ===========================================================================
// bf16 split scratch (static __device__ — allocation-free). 16B aligned.
// ===========================================================================
__device__ __align__(16) __nv_bfloat16 g_cat1_h[BB * SS * CATD];
__device__ __align__(16) __nv_bfloat16 g_cat1_l[BB * SS * CATD];
__device__ __align__(16) __nv_bfloat16 g_cat2_h[BB * SS * CATD];
__device__ __align__(16) __nv_bfloat16 g_cat2_l[BB * SS * CATD];

__device__ __align__(16) __nv_bfloat16 g_k1p_h[BB * SS * AD];
__device__ __align__(16) __nv_bfloat16 g_k1p_l[BB * SS * AD];
__device__ __align__(16) __nv_bfloat16 g_k2p_h[BB * SS * AD];
__device__ __align__(16) __nv_bfloat16 g_k2p_l[BB * SS * AD];
__device__ __align__(16) __nv_bfloat16 g_pk1_h[BB * SS * AD];
__device__ __align__(16) __nv_bfloat16 g_pk1_l[BB * SS * AD];
__device__ __align__(16) __nv_bfloat16 g_pk2_h[BB * SS * AD];
__device__ __align__(16) __nv_bfloat16 g_pk2_l[BB * SS * AD];

__device__ __align__(16) __nv_bfloat16 g_wtk1_h[AD * KD];
__device__ __align__(16) __nv_bfloat16 g_wtk1_l[AD * KD];
__device__ __align__(16) __nv_bfloat16 g_wtk2_h[AD * KD];
__device__ __align__(16) __nv_bfloat16 g_wtk2_l[AD * KD];
__device__ __align__(16) __nv_bfloat16 g_wtpk1_h[AD * CATD];
__device__ __align__(16) __nv_bfloat16 g_wtpk1_l[AD * CATD];
__device__ __align__(16) __nv_bfloat16 g_wtpk2_h[AD * CATD];
__device__ __align__(16) __nv_bfloat16 g_wtpk2_l[AD * CATD];

__device__ __align__(16) __nv_bfloat16 g_vt1_h[BB * DV * SS];
__device__ __align__(16) __nv_bfloat16 g_vt1_l[BB * DV * SS];
__device__ __align__(16) __nv_bfloat16 g_vt2_h[BB * DV * SS];
__device__ __align__(16) __nv_bfloat16 g_vt2_l[BB * DV * SS];

__device__ __align__(16) __nv_bfloat16 g_w1_h[BB * SS * SS];
__device__ __align__(16) __nv_bfloat16 g_w1_l[BB * SS * SS];
__device__ __align__(16) __nv_bfloat16 g_w2_h[BB * SS * SS];
__device__ __align__(16) __nv_bfloat16 g_w2_l[BB * SS * SS];

// ===========================================================================
// Helpers
// ===========================================================================
__device__ __forceinline__ uint32_t smem_u32(const void* p) {
    uint32_t a;
    asm("{ .reg .u64 t; cvta.to.shared.u64 t, %1; cvt.u32.u64 %0, t; }"
        : "=r"(a) : "l"(p));
    return a;
}

#define CP16(dst, src) \
    asm volatile("cp.async.cg.shared.global [%0], [%1], 16;" :: "r"(dst), "l"(src))
#define CP_COMMIT() asm volatile("cp.async.commit_group;" ::: "memory")
#define CP_WAIT1()  asm volatile("cp.async.wait_group 1;" ::: "memory")

#define LDSM_X4(r0, r1, r2, r3, addr) \
    asm volatile("ldmatrix.sync.aligned.m8n8.x4.shared.b16 {%0,%1,%2,%3}, [%4];" \
                 : "=r"(r0), "=r"(r1), "=r"(r2), "=r"(r3) : "r"(addr))

#define MMA16816(c, a, b0, b1) \
    asm volatile("mma.sync.aligned.m16n8k16.row.col.f32.bf16.bf16.f32 " \
                 "{%0,%1,%2,%3}, {%4,%5,%6,%7}, {%8,%9}, {%0,%1,%2,%3};" \
                 : "+f"((c)[0]), "+f"((c)[1]), "+f"((c)[2]), "+f"((c)[3]) \
                 : "r"((a)[0]), "r"((a)[1]), "r"((a)[2]), "r"((a)[3]), \
                   "r"(b0), "r"(b1))

__device__ __forceinline__ void split2(float x, __nv_bfloat16& h, __nv_bfloat16& l) {
    h = __float2bfloat16(x);
    l = __float2bfloat16(x - __bfloat162float(h));
}
__device__ __forceinline__ uint32_t pack_bf(__nv_bfloat16 a, __nv_bfloat16 b) {
    return ((uint32_t)__bfloat16_as_ushort(b) << 16) | (uint32_t)__bfloat16_as_ushort(a);
}

// Dtype-robust length read (lengths in [S/2,S); int64 LE view has arr[1]==0)
__device__ __forceinline__ int read_len(const int* __restrict__ arr, int b) {
    return (arr[1] == 0) ? arr[2 * b] : arr[b];
}

// ===========================================================================
// PERSISTENT bf16x3-split NT GEMM on mma.sync: C[m,n] = sum_k A[m,k]*B[n,k]
// grid = num_SMs CTAs; each CTA processes tiles bid, bid+nb, ... with ONE
// continuous cp.async chunk ring across tile boundaries (cold prologue paid
// once per CTA, not once per tile). Fragment/MMA core identical to R8.
// Tile decode: t -> (tx = t%gx, ty = (t/gx)%gy, tz = t/(gx*gy)); tz vs
// zsplit selects pointer-set (merged launches).
// mode 0: write fp32 C.  mode 1: bias-add then write split bf16 (Ch, Cl).
// ===========================================================================
#define GBM 128
#define GBN 128
#define GBK 64
#define NSTG 3
#define TILE_B (128 * 128)            // 16 KB: 128 rows x 128 B (64 bf16)
#define STAGE_B (4 * TILE_B)          // Ah, Al, Bh, Bl
#define SMEM_GEMM (128 + NSTG * STAGE_B)

__global__ __launch_bounds__(256, 1) void gemm_nt_mma(
    const __nv_bfloat16* __restrict__ Ah0, const __nv_bfloat16* __restrict__ Al0,
    const __nv_bfloat16* __restrict__ Bh0, const __nv_bfloat16* __restrict__ Bl0,
    float* __restrict__ Cf0, __nv_bfloat16* __restrict__ Ch0,
    __nv_bfloat16* __restrict__ Cl0, const float* __restrict__ bias0,
    const __nv_bfloat16* __restrict__ Ah1, const __nv_bfloat16* __restrict__ Al1,
    const __nv_bfloat16* __restrict__ Bh1, const __nv_bfloat16* __restrict__ Bl1,
    float* __restrict__ Cf1, __nv_bfloat16* __restrict__ Ch1,
    __nv_bfloat16* __restrict__ Cl1, const float* __restrict__ bias1,
    int zsplit,
    int ldA, long long bsA, int ldB, long long bsB,
    int Kred, long long bsC, int ldC, int mode,
    int gx, int gy, int ntiles)
{
    extern __shared__ char smem_raw[];
    uint32_t sb0 = smem_u32(smem_raw);
    uint32_t sbase = (sb0 + 127u) & ~127u;
    char* stages = smem_raw + (sbase - sb0);

    const int tid = threadIdx.x;
    const int lane = tid & 31;
    const int wid = tid >> 5;
    const int wm = wid & 1;            // 2 m-subtiles of 64
    const int wn = wid >> 1;           // 4 n-subtiles of 32

    const int nb = gridDim.x;
    const int bid = blockIdx.x;
    const int nch = Kred / GBK;
    const int mytiles = (bid < ntiles) ? ((ntiles - 1 - bid) / nb + 1) : 0;
    const int myQ = mytiles * nch;
    if (myQ == 0) return;

    float c[4][4][4];

    // ---- copy-lane geometry ----
    const int rr = tid >> 3;           // 0..31
    const int cc = tid & 7;            // 16B chunk within 128B row

    // issue chunk q of MY sequence: tile j = q/nch, k-chunk q%nch
    auto issue = [&](int q) {
        const int j = q / nch;
        const int kc = q - j * nch;
        const int t = bid + j * nb;
        const int tx = t % gx;
        const int rest = t / gx;
        const int ty = rest % gy;
        const int tz = rest / gy;
        const bool sec = tz >= zsplit;
        const long long bz = sec ? (tz - zsplit) : tz;
        const __nv_bfloat16* Ah = (sec ? Ah1 : Ah0) + bz * bsA;
        const __nv_bfloat16* Al = (sec ? Al1 : Al0) + bz * bsA;
        const __nv_bfloat16* Bh = (sec ? Bh1 : Bh0) + bz * bsB;
        const __nv_bfloat16* Bl = (sec ? Bl1 : Bl0) + bz * bsB;
        const int row0 = ty * GBM;
        const int col0 = tx * GBN;
        char* st = stages + (q % NSTG) * STAGE_B;
        const int k0 = kc * GBK;
#pragma unroll
        for (int p = 0; p < 4; p++) {
            const int row = rr + p * 32;
            const int sw = row * 128 + ((cc ^ (row & 7)) << 4);
            const uint32_t da = smem_u32(st + sw);
            const long long ka = (long long)(row0 + row) * ldA + k0 + cc * 8;
            const long long kb = (long long)(col0 + row) * ldB + k0 + cc * 8;
            CP16(da,                Ah + ka);
            CP16(da + TILE_B,       Al + ka);
            CP16(da + 2 * TILE_B,   Bh + kb);
            CP16(da + 3 * TILE_B,   Bl + kb);
        }
    };

    // ---- fragment-lane geometry ----
    const int a_r  = lane & 15;
    const int a_k2 = lane >> 4;
    const int b_r  = ((lane >> 4) << 3) + (lane & 7);
    const int b_k2 = (lane >> 3) & 1;

    auto compute = [&](int q) {
        const uint32_t stu = smem_u32(stages + (q % NSTG) * STAGE_B);
#pragma unroll
        for (int k16 = 0; k16 < GBK / 16; k16++) {
            uint32_t ah[4][4], al[4][4], bb[4][2];
#pragma unroll
            for (int mi = 0; mi < 4; mi++) {
                const int row = wm * 64 + mi * 16 + a_r;
                const int kch = k16 * 2 + a_k2;
                const uint32_t off = row * 128 + ((kch ^ (row & 7)) << 4);
                LDSM_X4(ah[mi][0], ah[mi][1], ah[mi][2], ah[mi][3], stu + off);
                LDSM_X4(al[mi][0], al[mi][1], al[mi][2], al[mi][3],
                        stu + TILE_B + off);
            }
#pragma unroll
            for (int pi = 0; pi < 2; pi++) {
                const int n = wn * 32 + pi * 16 + b_r;
                const int kch = k16 * 2 + b_k2;
                const uint32_t off = n * 128 + ((kch ^ (n & 7)) << 4);
                uint32_t t0, t1, t2, t3;
                LDSM_X4(t0, t1, t2, t3, stu + 2 * TILE_B + off);
                bb[2 * pi][0] = t0;     bb[2 * pi][1] = t1;
                bb[2 * pi + 1][0] = t2; bb[2 * pi + 1][1] = t3;
            }
#pragma unroll
            for (int mi = 0; mi < 4; mi++)
#pragma unroll
                for (int ni = 0; ni < 4; ni++)
                    MMA16816(c[mi][ni], ah[mi], bb[ni][0], bb[ni][1]);
#pragma unroll
            for (int mi = 0; mi < 4; mi++)
#pragma unroll
                for (int ni = 0; ni < 4; ni++)
                    MMA16816(c[mi][ni], al[mi], bb[ni][0], bb[ni][1]);
#pragma unroll
            for (int pi = 0; pi < 2; pi++) {
                const int n = wn * 32 + pi * 16 + b_r;
                const int kch = k16 * 2 + b_k2;
                const uint32_t off = n * 128 + ((kch ^ (n & 7)) << 4);
                uint32_t t0, t1, t2, t3;
                LDSM_X4(t0, t1, t2, t3, stu + 3 * TILE_B + off);
                bb[2 * pi][0] = t0;     bb[2 * pi][1] = t1;
                bb[2 * pi + 1][0] = t2; bb[2 * pi + 1][1] = t3;
            }
#pragma unroll
            for (int mi = 0; mi < 4; mi++)
#pragma unroll
                for (int ni = 0; ni < 4; ni++)
                    MMA16816(c[mi][ni], ah[mi], bb[ni][0], bb[ni][1]);
        }
    };

    const int rr4 = lane >> 2;
    const int cc2 = (lane & 3) * 2;

    // epilogue for my local tile j (registers -> global; no smem, no barrier)
    auto epilogue = [&](int j) {
        const int t = bid + j * nb;
        const int tx = t % gx;
        const int rest = t / gx;
        const int ty = rest % gy;
        const int tz = rest / gy;
        const bool sec = tz >= zsplit;
        const long long bz = sec ? (tz - zsplit) : tz;
        const int r_base = ty * GBM + wm * 64;
        const int c_base = tx * GBN + wn * 32;

        if (mode == 0) {
            float* out = (sec ? Cf1 : Cf0) + bz * bsC;
#pragma unroll
            for (int mi = 0; mi < 4; mi++)
#pragma unroll
                for (int ni = 0; ni < 4; ni++) {
                    const int r = r_base + mi * 16 + rr4;
                    const int col = c_base + ni * 8 + cc2;
                    *(float2*)(out + (long long)r * ldC + col) =
                        make_float2(c[mi][ni][0], c[mi][ni][1]);
                    *(float2*)(out + (long long)(r + 8) * ldC + col) =
                        make_float2(c[mi][ni][2], c[mi][ni][3]);
                }
        } else {
            __nv_bfloat16* Ch = sec ? Ch1 : Ch0;
            __nv_bfloat16* Cl = sec ? Cl1 : Cl0;
            const float* bias = sec ? bias1 : bias0;
#pragma unroll
            for (int mi = 0; mi < 4; mi++)
#pragma unroll
                for (int ni = 0; ni < 4; ni++) {
                    const int r = r_base + mi * 16 + rr4;
                    const int col = c_base + ni * 8 + cc2;
                    const float bx = bias[col], by = bias[col + 1];
                    float x0 = c[mi][ni][0] + bx, x1 = c[mi][ni][1] + by;
                    float x2 = c[mi][ni][2] + bx, x3 = c[mi][ni][3] + by;
                    __nv_bfloat16 h0, l0, h1, l1;
                    split2(x0, h0, l0); split2(x1, h1, l1);
                    *(uint32_t*)(Ch + (long long)r * ldC + col) = pack_bf(h0, h1);
                    *(uint32_t*)(Cl + (long long)r * ldC + col) = pack_bf(l0, l1);
                    split2(x2, h0, l0); split2(x3, h1, l1);
                    *(uint32_t*)(Ch + (long long)(r + 8) * ldC + col) = pack_bf(h0, h1);
                    *(uint32_t*)(Cl + (long long)(r + 8) * ldC + col) = pack_bf(l0, l1);
                }
        }
    };

    // ---- ONE continuous pipeline across all my tiles ----
    issue(0); CP_COMMIT();
    if (myQ > 1) issue(1);
    CP_COMMIT();

    int kcnt = 0, jcur = 0;
    for (int q = 0; q < myQ; q++) {
        CP_WAIT1();
        __syncthreads();
        if (q + 2 < myQ) issue(q + 2);
        CP_COMMIT();
        if (kcnt == 0) {
#pragma unroll
            for (int mi = 0; mi < 4; mi++)
#pragma unroll
                for (int ni = 0; ni < 4; ni++)
#pragma unroll
                    for (int qq = 0; qq < 4; qq++) c[mi][ni][qq] = 0.f;
        }
        compute(q);
        if (++kcnt == nch) {
            kcnt = 0;
            epilogue(jcur);
            jcur++;
        }
    }
}

// ===========================================================================
// ONE fused prep kernel: all transposes + concat splits, block-range dispatch.
// ===========================================================================
#define NB_WTK   512
#define NB_WTPK  768
#define NB_VT    16384
#define NB_CAT   24576
#define NB_PREP  (NB_WTK + NB_WTPK + NB_VT + NB_CAT)

__device__ __forceinline__ void transpose_tile(
    float (*tile)[33],
    const float* __restrict__ src, __nv_bfloat16* __restrict__ dh,
    __nv_bfloat16* __restrict__ dl, int R, int C, int tr, int tc)
{
    const int x = threadIdx.x & 31;
    const int y0 = threadIdx.x >> 5;       // 0..7
    const int r0 = tr * 32, c0 = tc * 32;
#pragma unroll
    for (int dy = 0; dy < 32; dy += 8)
        tile[y0 + dy][x] = src[(long long)(r0 + y0 + dy) * C + c0 + x];
    __syncthreads();
#pragma unroll
    for (int dy = 0; dy < 32; dy += 8) {
        const int c = c0 + y0 + dy;
        float v = tile[x][y0 + dy];
        __nv_bfloat16 h, l;
        split2(v, h, l);
        dh[(long long)c * R + r0 + x] = h;
        dl[(long long)c * R + r0 + x] = l;
    }
}

__global__ __launch_bounds__(256) void prep_kernel(
    const float* __restrict__ k1,  const float* __restrict__ pk1c,
    const float* __restrict__ k2,  const float* __restrict__ pk2c,
    const float* __restrict__ v1,  const float* __restrict__ v2,
    const float* __restrict__ W_k1, const float* __restrict__ W_k2,
    const float* __restrict__ W_pk1, const float* __restrict__ W_pk2)
{
    __shared__ float tile[32][33];
    const int b = blockIdx.x;
    const int tid = threadIdx.x;

    if (b < NB_WTK) {
        const int side = b >> 8;
        const int rem = b & 255;
        const int tr = rem >> 4, tc = rem & 15;
        transpose_tile(tile,
                       side ? W_k2 : W_k1,
                       side ? g_wtk2_h : g_wtk1_h,
                       side ? g_wtk2_l : g_wtk1_l,
                       KD, AD, tr, tc);
        return;
    }
    if (b < NB_WTK + NB_WTPK) {
        const int bb2 = b - NB_WTK;
        const int side = bb2 / 384;
        const int rem = bb2 - side * 384;
        const int tr = rem >> 4, tc = rem & 15;    // 24 x 16
        transpose_tile(tile,
                       side ? W_pk2 : W_pk1,
                       side ? g_wtpk2_h : g_wtpk1_h,
                       side ? g_wtpk2_l : g_wtpk1_l,
                       CATD, AD, tr, tc);
        return;
    }
    if (b < NB_WTK + NB_WTPK + NB_VT) {
        const int bb2 = b - (NB_WTK + NB_WTPK);
        const int z = bb2 >> 10;                   // 0..15
        const int rem = bb2 & 1023;
        const int tr = rem >> 4, tc = rem & 15;    // 64 x 16
        const bool second = z >= BB;
        const long long batch = second ? (z - BB) : z;
        const float* src = (second ? v2 : v1) + batch * (long long)SS * DV;
        __nv_bfloat16* dh = (second ? g_vt2_h : g_vt1_h) + batch * (long long)DV * SS;
        __nv_bfloat16* dl = (second ? g_vt2_l : g_vt1_l) + batch * (long long)DV * SS;
        transpose_tile(tile, src, dh, dl, SS, DV, tr, tc);
        return;
    }

    const int chunks = CATD / 4;                   // 192 per row
    const int Mtot = BB * SS;
    long long idx = (long long)(b - (NB_WTK + NB_WTPK + NB_VT)) * 256 + tid;
    const long long per_side = (long long)Mtot * chunks;
    const bool side2 = idx >= per_side;
    if (side2) idx -= per_side;
    const int r = (int)(idx / chunks);
    const int c = (int)(idx - (long long)r * chunks) * 4;

    const float* kk = side2 ? k2 : k1;
    const float* pp = side2 ? pk2c : pk1c;
    __nv_bfloat16* dh = side2 ? g_cat2_h : g_cat1_h;
    __nv_bfloat16* dl = side2 ? g_cat2_l : g_cat1_l;

    float4 v;
    if (c < KD) v = *(const float4*)(kk + (long long)r * KD + c);
    else        v = *(const float4*)(pp + (long long)r * PKD + (c - KD));

    __nv_bfloat16 h0, l0, h1, l1, h2, l2, h3, l3;
    split2(v.x, h0, l0); split2(v.y, h1, l1);
    split2(v.z, h2, l2); split2(v.w, h3, l3);
    long long base = (long long)r * CATD + c;
    *(uint2*)(dh + base) = make_uint2(pack_bf(h0, h1), pack_bf(h2, h3));
    *(uint2*)(dl + base) = make_uint2(pack_bf(l0, l1), pack_bf(l2, l3));
}

// ===========================================================================
// Masked in-place row softmax + fused bf16 split; both w matrices in one
// launch: blockIdx.y in [0,2*BB): y < BB -> w1 (lenR=l2,lenC=l1), else w2.
// ===========================================================================
__global__ __launch_bounds__(256) void softmax_mask_split_kernel(
    float* __restrict__ W1, float* __restrict__ W2,
    const int* __restrict__ l1, const int* __restrict__ l2)
{
    const int yraw = blockIdx.y;
    const bool second = yraw >= BB;
    const int b = second ? (yraw - BB) : yraw;
    float* W = second ? W2 : W1;
    __nv_bfloat16* Wh = second ? g_w2_h : g_w1_h;
    __nv_bfloat16* Wl = second ? g_w2_l : g_w1_l;
    const int* lenR = second ? l1 : l2;
    const int* lenC = second ? l2 : l1;

    const int r = blockIdx.x;
    const long long rowoff = ((long long)b * SS + r) * (long long)SS;
    float* row = W + rowoff;
    const int lc = read_len(lenC, b);
    const bool rover = r >= read_len(lenR, b);
    const int tid = threadIdx.x;
    const int c0 = tid * 8;

    float vals[8];
    float4 v0 = *(float4*)(row + c0);
    float4 v1 = *(float4*)(row + c0 + 4);
    vals[0] = v0.x; vals[1] = v0.y; vals[2] = v0.z; vals[3] = v0.w;
    vals[4] = v1.x; vals[5] = v1.y; vals[6] = v1.z; vals[7] = v1.w;

    float m = -CUDART_INF_F;
#pragma unroll
    for (int i = 0; i < 8; i++) {
        bool cover = (c0 + i) >= lc;
        if (cover != rover) vals[i] = -CUDART_INF_F;   // XOR mask semantics
        m = fmaxf(m, vals[i]);
    }

    const int lane = tid & 31, wrp = tid >> 5;
    __shared__ float smax[8];
    __shared__ float ssum[8];
#pragma unroll
    for (int o = 16; o; o >>= 1) m = fmaxf(m, __shfl_xor_sync(0xffffffffu, m, o));
    if (!lane) smax[wrp] = m;
    __syncthreads();
    m = smax[0];
#pragma unroll
    for (int i = 1; i < 8; i++) m = fmaxf(m, smax[i]);

    float s = 0.f;
#pragma unroll
    for (int i = 0; i < 8; i++) {
        vals[i] = __expf(vals[i] - m);
        s += vals[i];
    }
#pragma unroll
    for (int o = 16; o; o >>= 1) s += __shfl_xor_sync(0xffffffffu, s, o);
    if (!lane) ssum[wrp] = s;
    __syncthreads();
    s = ssum[0];
#pragma unroll
    for (int i = 1; i < 8; i++) s += ssum[i];
    const float inv = 1.f / s;

    uint32_t hiw[4], low[4];
#pragma unroll
    for (int i = 0; i < 8; i++) vals[i] *= inv;
#pragma unroll
    for (int j = 0; j < 4; j++) {
        __nv_bfloat16 h0, l0, h1, l1;
        split2(vals[2 * j + 0], h0, l0);
        split2(vals[2 * j + 1], h1, l1);
        hiw[j] = pack_bf(h0, h1);
        low[j] = pack_bf(l0, l1);
    }

    v0.x = vals[0]; v0.y = vals[1]; v0.z = vals[2]; v0.w = vals[3];
    v1.x = vals[4]; v1.y = vals[5]; v1.z = vals[6]; v1.w = vals[7];
    *(float4*)(row + c0) = v0;
    *(float4*)(row + c0 + 4) = v1;
    *(uint4*)(Wh + rowoff + c0) = make_uint4(hiw[0], hiw[1], hiw[2], hiw[3]);
    *(uint4*)(Wl + rowoff + c0) = make_uint4(low[0], low[1], low[2], low[3]);
}

// ===========================================================================
// Launch
// ===========================================================================
extern "C" void kernel_launch(void* const* d_in, const int* in_sizes, int n_in,
                              void* d_out, int out_size)
{
    const float* k1   = (const float*)d_in[0];
    const float* k2   = (const float*)d_in[1];
    const float* pk1c = (const float*)d_in[2];
    const float* pk2c = (const float*)d_in[3];
    const float* v1   = (const float*)d_in[4];
    const float* v2   = (const float*)d_in[5];
    const float* W_k1  = (const float*)d_in[6];
    const float* b_k1  = (const float*)d_in[7];
    const float* W_k2  = (const float*)d_in[8];
    const float* b_k2  = (const float*)d_in[9];
    const float* W_pk1 = (const float*)d_in[10];
    const float* b_pk1 = (const float*)d_in[11];
    const float* W_pk2 = (const float*)d_in[12];
    const float* b_pk2 = (const float*)d_in[13];
    const int* l1 = (const int*)d_in[14];
    const int* l2 = (const int*)d_in[15];

    float* o1 = (float*)d_out;                               // [B,S2,DV]
    float* o2 = o1 + (long long)BB * SS * DV;                // [B,S1,DV]
    float* w1 = o2 + (long long)BB * SS * DV;                // [B,S2,S1]
    float* w2 = w1 + (long long)BB * SS * SS;                // [B,S1,S2]

    __nv_bfloat16 *cat1h, *cat1l, *cat2h, *cat2l;
    __nv_bfloat16 *k1ph, *k1pl, *k2ph, *k2pl, *pk1h, *pk1l, *pk2h, *pk2l;
    __nv_bfloat16 *wtk1h, *wtk1l, *wtk2h, *wtk2l, *wtpk1h, *wtpk1l, *wtpk2h, *wtpk2l;
    __nv_bfloat16 *vt1h, *vt1l, *vt2h, *vt2l;
    __nv_bfloat16 *w1h, *w1l, *w2h, *w2l;
    cudaGetSymbolAddress((void**)&cat1h, g_cat1_h); cudaGetSymbolAddress((void**)&cat1l, g_cat1_l);
    cudaGetSymbolAddress((void**)&cat2h, g_cat2_h); cudaGetSymbolAddress((void**)&cat2l, g_cat2_l);
    cudaGetSymbolAddress((void**)&k1ph, g_k1p_h);   cudaGetSymbolAddress((void**)&k1pl, g_k1p_l);
    cudaGetSymbolAddress((void**)&k2ph, g_k2p_h);   cudaGetSymbolAddress((void**)&k2pl, g_k2p_l);
    cudaGetSymbolAddress((void**)&pk1h, g_pk1_h);   cudaGetSymbolAddress((void**)&pk1l, g_pk1_l);
    cudaGetSymbolAddress((void**)&pk2h, g_pk2_h);   cudaGetSymbolAddress((void**)&pk2l, g_pk2_l);
    cudaGetSymbolAddress((void**)&wtk1h, g_wtk1_h); cudaGetSymbolAddress((void**)&wtk1l, g_wtk1_l);
    cudaGetSymbolAddress((void**)&wtk2h, g_wtk2_h); cudaGetSymbolAddress((void**)&wtk2l, g_wtk2_l);
    cudaGetSymbolAddress((void**)&wtpk1h, g_wtpk1_h); cudaGetSymbolAddress((void**)&wtpk1l, g_wtpk1_l);
    cudaGetSymbolAddress((void**)&wtpk2h, g_wtpk2_h); cudaGetSymbolAddress((void**)&wtpk2l, g_wtpk2_l);
    cudaGetSymbolAddress((void**)&vt1h, g_vt1_h);   cudaGetSymbolAddress((void**)&vt1l, g_vt1_l);
    cudaGetSymbolAddress((void**)&vt2h, g_vt2_h);   cudaGetSymbolAddress((void**)&vt2l, g_vt2_l);
    cudaGetSymbolAddress((void**)&w1h, g_w1_h);     cudaGetSymbolAddress((void**)&w1l, g_w1_l);
    cudaGetSymbolAddress((void**)&w2h, g_w2_h);     cudaGetSymbolAddress((void**)&w2l, g_w2_l);

    cudaFuncSetAttribute(gemm_nt_mma,
                         cudaFuncAttributeMaxDynamicSharedMemorySize, SMEM_GEMM);

    static int nsm = 0;
    if (nsm == 0) {
        int dev = 0;
        cudaGetDevice(&dev);
        if (cudaDeviceGetAttribute(&nsm, cudaDevAttrMultiProcessorCount, dev)
                != cudaSuccess || nsm <= 0)
            nsm = 148;
    }

    const int Mtot = BB * SS;   // 16384

    // (1) ALL preprocessing in one launch
    prep_kernel<<<NB_PREP, 256>>>(k1, pk1c, k2, pk2c, v1, v2,
                                  W_k1, W_k2, W_pk1, W_pk2);

    // (2) k-projection GEMMs (persistent, z=2): k1p, k2p
    //     tiles: gx=AD/128=4, gy=Mtot/128=128, ntiles=4*128*2
    gemm_nt_mma<<<nsm, 256, SMEM_GEMM>>>(
        cat1h, cat1l, wtk1h, wtk1l, nullptr, k1ph, k1pl, b_k1,
        cat2h, cat2l, wtk2h, wtk2l, nullptr, k2ph, k2pl, b_k2,
        1, CATD, 0, KD, 0, KD, 0, AD, 1,
        AD / GBN, Mtot / GBM, (AD / GBN) * (Mtot / GBM) * 2);

    // (3) pk-projection GEMMs (persistent, z=2): pk1, pk2
    gemm_nt_mma<<<nsm, 256, SMEM_GEMM>>>(
        cat1h, cat1l, wtpk1h, wtpk1l, nullptr, pk1h, pk1l, b_pk1,
        cat2h, cat2l, wtpk2h, wtpk2l, nullptr, pk2h, pk2l, b_pk2,
        1, CATD, 0, CATD, 0, CATD, 0, AD, 1,
        AD / GBN, Mtot / GBM, (AD / GBN) * (Mtot / GBM) * 2);

    // (4) score GEMMs (persistent, z=16, fp32 into w regions)
    //     w1_pre[t,s] = pk2[t,:].k1p[s,:]   w2_pre[s,t] = pk1[s,:].k2p[t,:]
    gemm_nt_mma<<<nsm, 256, SMEM_GEMM>>>(
        pk2h, pk2l, k1ph, k1pl, w1, nullptr, nullptr, nullptr,
        pk1h, pk1l, k2ph, k2pl, w2, nullptr, nullptr, nullptr,
        BB, AD, (long long)SS * AD, AD, (long long)SS * AD,
        AD, (long long)SS * SS, SS, 0,
        SS / GBN, SS / GBM, (SS / GBN) * (SS / GBM) * 2 * BB);

    // (5) masked softmax + split, both w matrices (grid.y = 16)
    softmax_mask_split_kernel<<<dim3(SS, 2 * BB), 256>>>(w1, w2, l1, l2);

    // (6) output GEMMs (persistent, z=16): o1 = w1 @ v1, o2 = w2 @ v2
    gemm_nt_mma<<<nsm, 256, SMEM_GEMM>>>(
        w1h, w1l, vt1h, vt1l, o1, nullptr, nullptr, nullptr,
        w2h, w2l, vt2h, vt2l, o2, nullptr, nullptr, nullptr,
        BB, SS, (long long)SS * SS, SS, (long long)DV * SS,
        SS, (long long)SS * DV, DV, 0,
        DV / GBN, SS / GBM, (DV / GBN) * (SS / GBM) * 2 * BB);
}

// round 13
// speedup vs baseline: 1.0960x; 1.0960x over previous
#include <cuda_runtime.h>
#include <cuda_bf16.h>
#include <math_constants.h>
#include <cstdint>

// Problem dims
#define BB 8
#define SS 2048      // S1 == S2
#define KD 512       // K1_DIM == K2_DIM
#define PKD 256
#define CATD 768     // KD + PKD
#define AD 512       // ATT_DIM
#define DV 512

// ===========================================================================
// bf16 split scratch (static __device__ — allocation-free). 16B aligned.
// ===========================================================================
__device__ __align__(16) __nv_bfloat16 g_cat1_h[BB * SS * CATD];
__device__ __align__(16) __nv_bfloat16 g_cat1_l[BB * SS * CATD];
__device__ __align__(16) __nv_bfloat16 g_cat2_h[BB * SS * CATD];
__device__ __align__(16) __nv_bfloat16 g_cat2_l[BB * SS * CATD];

__device__ __align__(16) __nv_bfloat16 g_k1p_h[BB * SS * AD];
__device__ __align__(16) __nv_bfloat16 g_k1p_l[BB * SS * AD];
__device__ __align__(16) __nv_bfloat16 g_k2p_h[BB * SS * AD];
__device__ __align__(16) __nv_bfloat16 g_k2p_l[BB * SS * AD];
__device__ __align__(16) __nv_bfloat16 g_pk1_h[BB * SS * AD];
__device__ __align__(16) __nv_bfloat16 g_pk1_l[BB * SS * AD];
__device__ __align__(16) __nv_bfloat16 g_pk2_h[BB * SS * AD];
__device__ __align__(16) __nv_bfloat16 g_pk2_l[BB * SS * AD];

__device__ __align__(16) __nv_bfloat16 g_wtk1_h[AD * KD];
__device__ __align__(16) __nv_bfloat16 g_wtk1_l[AD * KD];
__device__ __align__(16) __nv_bfloat16 g_wtk2_h[AD * KD];
__device__ __align__(16) __nv_bfloat16 g_wtk2_l[AD * KD];
__device__ __align__(16) __nv_bfloat16 g_wtpk1_h[AD * CATD];
__device__ __align__(16) __nv_bfloat16 g_wtpk1_l[AD * CATD];
__device__ __align__(16) __nv_bfloat16 g_wtpk2_h[AD * CATD];
__device__ __align__(16) __nv_bfloat16 g_wtpk2_l[AD * CATD];

__device__ __align__(16) __nv_bfloat16 g_vt1_h[BB * DV * SS];
__device__ __align__(16) __nv_bfloat16 g_vt1_l[BB * DV * SS];
__device__ __align__(16) __nv_bfloat16 g_vt2_h[BB * DV * SS];
__device__ __align__(16) __nv_bfloat16 g_vt2_l[BB * DV * SS];

__device__ __align__(16) __nv_bfloat16 g_w1_h[BB * SS * SS];
__device__ __align__(16) __nv_bfloat16 g_w1_l[BB * SS * SS];
__device__ __align__(16) __nv_bfloat16 g_w2_h[BB * SS * SS];
__device__ __align__(16) __nv_bfloat16 g_w2_l[BB * SS * SS];

// ===========================================================================
// Helpers
// ===========================================================================
__device__ __forceinline__ uint32_t smem_u32(const void* p) {
    uint32_t a;
    asm("{ .reg .u64 t; cvta.to.shared.u64 t, %1; cvt.u32.u64 %0, t; }"
        : "=r"(a) : "l"(p));
    return a;
}

#define CP16(dst, src) \
    asm volatile("cp.async.cg.shared.global [%0], [%1], 16;" :: "r"(dst), "l"(src))
#define CP_COMMIT() asm volatile("cp.async.commit_group;" ::: "memory")
#define CP_WAIT1()  asm volatile("cp.async.wait_group 1;" ::: "memory")

#define LDSM_X4(r0, r1, r2, r3, addr) \
    asm volatile("ldmatrix.sync.aligned.m8n8.x4.shared.b16 {%0,%1,%2,%3}, [%4];" \
                 : "=r"(r0), "=r"(r1), "=r"(r2), "=r"(r3) : "r"(addr))

#define MMA16816(c, a, b0, b1) \
    asm volatile("mma.sync.aligned.m16n8k16.row.col.f32.bf16.bf16.f32 " \
                 "{%0,%1,%2,%3}, {%4,%5,%6,%7}, {%8,%9}, {%0,%1,%2,%3};" \
                 : "+f"((c)[0]), "+f"((c)[1]), "+f"((c)[2]), "+f"((c)[3]) \
                 : "r"((a)[0]), "r"((a)[1]), "r"((a)[2]), "r"((a)[3]), \
                   "r"(b0), "r"(b1))

__device__ __forceinline__ void split2(float x, __nv_bfloat16& h, __nv_bfloat16& l) {
    h = __float2bfloat16(x);
    l = __float2bfloat16(x - __bfloat162float(h));
}
__device__ __forceinline__ uint32_t pack_bf(__nv_bfloat16 a, __nv_bfloat16 b) {
    return ((uint32_t)__bfloat16_as_ushort(b) << 16) | (uint32_t)__bfloat16_as_ushort(a);
}

// Dtype-robust length read (lengths in [S/2,S); int64 LE view has arr[1]==0)
__device__ __forceinline__ int read_len(const int* __restrict__ arr, int b) {
    return (arr[1] == 0) ? arr[2 * b] : arr[b];
}

// ===========================================================================
// PERSISTENT bf16x3-split NT GEMM, register-disciplined restructure:
// - nested loops: tile decode (div/mod) ONCE per tile, not per chunk
// - exactly two tile states live (cur/next): 4 operand ptrs + row/col/tz
// - epilogue at tile level (outside chunk loop) -> accumulators don't
//   overlap issue temps; next tile's first 2 chunks are in flight while
//   the epilogue drains (cold-prologue hiding)
// - cp.async ring (3 stages) continuous across tile boundaries via
//   incremental stage counters si/sc
// Fragment/MMA/swizzle core identical to the proven R10 kernel.
// ===========================================================================
#define GBM 128
#define GBN 128
#define GBK 64
#define NSTG 3
#define TILE_B (128 * 128)            // 16 KB: 128 rows x 128 B (64 bf16)
#define STAGE_B (4 * TILE_B)          // Ah, Al, Bh, Bl
#define SMEM_GEMM (128 + NSTG * STAGE_B)

__global__ __launch_bounds__(256, 1) void gemm_nt_mma(
    const __nv_bfloat16* __restrict__ Ah0, const __nv_bfloat16* __restrict__ Al0,
    const __nv_bfloat16* __restrict__ Bh0, const __nv_bfloat16* __restrict__ Bl0,
    float* __restrict__ Cf0, __nv_bfloat16* __restrict__ Ch0,
    __nv_bfloat16* __restrict__ Cl0, const float* __restrict__ bias0,
    const __nv_bfloat16* __restrict__ Ah1, const __nv_bfloat16* __restrict__ Al1,
    const __nv_bfloat16* __restrict__ Bh1, const __nv_bfloat16* __restrict__ Bl1,
    float* __restrict__ Cf1, __nv_bfloat16* __restrict__ Ch1,
    __nv_bfloat16* __restrict__ Cl1, const float* __restrict__ bias1,
    int zsplit,
    int ldA, long long bsA, int ldB, long long bsB,
    int Kred, long long bsC, int ldC, int mode,
    int gx, int gy, int ntiles)
{
    extern __shared__ char smem_raw[];
    uint32_t sb0 = smem_u32(smem_raw);
    uint32_t sbase = (sb0 + 127u) & ~127u;
    char* stages = smem_raw + (sbase - sb0);

    const int tid = threadIdx.x;
    const int lane = tid & 31;
    const int wid = tid >> 5;
    const int wm = wid & 1;            // 2 m-subtiles of 64
    const int wn = wid >> 1;           // 4 n-subtiles of 32

    const int nb = gridDim.x;
    const int bid = blockIdx.x;
    const int nch = Kred / GBK;        // >= 4 always here
    const int mytiles = (bid < ntiles) ? ((ntiles - 1 - bid) / nb + 1) : 0;
    if (mytiles == 0) return;

    // ---- copy-lane geometry ----
    const int rr = tid >> 3;           // 0..31
    const int cc = tid & 7;            // 16B chunk within 128B row

    // ---- fragment-lane geometry ----
    const int a_r  = lane & 15;
    const int a_k2 = lane >> 4;
    const int b_r  = ((lane >> 4) << 3) + (lane & 7);
    const int b_k2 = (lane >> 3) & 1;

    // decode tile id -> operand pointers + row/col/tz (once per tile)
    auto decode = [&](int t,
                      const __nv_bfloat16*& pAh, const __nv_bfloat16*& pAl,
                      const __nv_bfloat16*& pBh, const __nv_bfloat16*& pBl,
                      int& row0, int& col0, int& tzv) {
        const int tx = t % gx;
        const int rest = t / gx;
        const int ty = rest % gy;
        const int tz = rest / gy;
        const bool sec = tz >= zsplit;
        const long long bz = sec ? (tz - zsplit) : tz;
        pAh = (sec ? Ah1 : Ah0) + bz * bsA;
        pAl = (sec ? Al1 : Al0) + bz * bsA;
        pBh = (sec ? Bh1 : Bh0) + bz * bsB;
        pBl = (sec ? Bl1 : Bl0) + bz * bsB;
        row0 = ty * GBM;
        col0 = tx * GBN;
        tzv = tz;
    };

    auto issue = [&](int s,
                     const __nv_bfloat16* pAh, const __nv_bfloat16* pAl,
                     const __nv_bfloat16* pBh, const __nv_bfloat16* pBl,
                     int row0, int col0, int k0) {
        char* st = stages + s * STAGE_B;
#pragma unroll
        for (int p = 0; p < 4; p++) {
            const int row = rr + p * 32;
            const int sw = row * 128 + ((cc ^ (row & 7)) << 4);
            const uint32_t da = smem_u32(st + sw);
            const long long ka = (long long)(row0 + row) * ldA + k0 + cc * 8;
            const long long kb = (long long)(col0 + row) * ldB + k0 + cc * 8;
            CP16(da,                pAh + ka);
            CP16(da + TILE_B,       pAl + ka);
            CP16(da + 2 * TILE_B,   pBh + kb);
            CP16(da + 3 * TILE_B,   pBl + kb);
        }
    };

    float c[4][4][4];

    auto compute = [&](int s) {
        const uint32_t stu = smem_u32(stages + s * STAGE_B);
#pragma unroll
        for (int k16 = 0; k16 < GBK / 16; k16++) {
            uint32_t ah[4][4], al[4][4], bb[4][2];
#pragma unroll
            for (int mi = 0; mi < 4; mi++) {
                const int row = wm * 64 + mi * 16 + a_r;
                const int kch = k16 * 2 + a_k2;
                const uint32_t off = row * 128 + ((kch ^ (row & 7)) << 4);
                LDSM_X4(ah[mi][0], ah[mi][1], ah[mi][2], ah[mi][3], stu + off);
                LDSM_X4(al[mi][0], al[mi][1], al[mi][2], al[mi][3],
                        stu + TILE_B + off);
            }
#pragma unroll
            for (int pi = 0; pi < 2; pi++) {
                const int n = wn * 32 + pi * 16 + b_r;
                const int kch = k16 * 2 + b_k2;
                const uint32_t off = n * 128 + ((kch ^ (n & 7)) << 4);
                uint32_t t0, t1, t2, t3;
                LDSM_X4(t0, t1, t2, t3, stu + 2 * TILE_B + off);
                bb[2 * pi][0] = t0;     bb[2 * pi][1] = t1;
                bb[2 * pi + 1][0] = t2; bb[2 * pi + 1][1] = t3;
            }
#pragma unroll
            for (int mi = 0; mi < 4; mi++)
#pragma unroll
                for (int ni = 0; ni < 4; ni++)
                    MMA16816(c[mi][ni], ah[mi], bb[ni][0], bb[ni][1]);
#pragma unroll
            for (int mi = 0; mi < 4; mi++)
#pragma unroll
                for (int ni = 0; ni < 4; ni++)
                    MMA16816(c[mi][ni], al[mi], bb[ni][0], bb[ni][1]);
#pragma unroll
            for (int pi = 0; pi < 2; pi++) {
                const int n = wn * 32 + pi * 16 + b_r;
                const int kch = k16 * 2 + b_k2;
                const uint32_t off = n * 128 + ((kch ^ (n & 7)) << 4);
                uint32_t t0, t1, t2, t3;
                LDSM_X4(t0, t1, t2, t3, stu + 3 * TILE_B + off);
                bb[2 * pi][0] = t0;     bb[2 * pi][1] = t1;
                bb[2 * pi + 1][0] = t2; bb[2 * pi + 1][1] = t3;
            }
#pragma unroll
            for (int mi = 0; mi < 4; mi++)
#pragma unroll
                for (int ni = 0; ni < 4; ni++)
                    MMA16816(c[mi][ni], ah[mi], bb[ni][0], bb[ni][1]);
        }
    };

    const int rr4 = lane >> 2;
    const int cc2 = (lane & 3) * 2;

    auto epilogue = [&](int tz, int row0, int col0) {
        const bool sec = tz >= zsplit;
        const long long bz = sec ? (tz - zsplit) : tz;
        const int r_base = row0 + wm * 64;
        const int c_base = col0 + wn * 32;
        if (mode == 0) {
            float* out = (sec ? Cf1 : Cf0) + bz * bsC;
#pragma unroll
            for (int mi = 0; mi < 4; mi++)
#pragma unroll
                for (int ni = 0; ni < 4; ni++) {
                    const int r = r_base + mi * 16 + rr4;
                    const int col = c_base + ni * 8 + cc2;
                    *(float2*)(out + (long long)r * ldC + col) =
                        make_float2(c[mi][ni][0], c[mi][ni][1]);
                    *(float2*)(out + (long long)(r + 8) * ldC + col) =
                        make_float2(c[mi][ni][2], c[mi][ni][3]);
                }
        } else {
            __nv_bfloat16* Ch = sec ? Ch1 : Ch0;
            __nv_bfloat16* Cl = sec ? Cl1 : Cl0;
            const float* bias = sec ? bias1 : bias0;
#pragma unroll
            for (int mi = 0; mi < 4; mi++)
#pragma unroll
                for (int ni = 0; ni < 4; ni++) {
                    const int r = r_base + mi * 16 + rr4;
                    const int col = c_base + ni * 8 + cc2;
                    const float bx = bias[col], by = bias[col + 1];
                    float x0 = c[mi][ni][0] + bx, x1 = c[mi][ni][1] + by;
                    float x2 = c[mi][ni][2] + bx, x3 = c[mi][ni][3] + by;
                    __nv_bfloat16 h0, l0, h1, l1;
                    split2(x0, h0, l0); split2(x1, h1, l1);
                    *(uint32_t*)(Ch + (long long)r * ldC + col) = pack_bf(h0, h1);
                    *(uint32_t*)(Cl + (long long)r * ldC + col) = pack_bf(l0, l1);
                    split2(x2, h0, l0); split2(x3, h1, l1);
                    *(uint32_t*)(Ch + (long long)(r + 8) * ldC + col) = pack_bf(h0, h1);
                    *(uint32_t*)(Cl + (long long)(r + 8) * ldC + col) = pack_bf(l0, l1);
                }
        }
    };

    // ---- two live tile states ----
    const __nv_bfloat16 *cAh, *cAl, *cBh, *cBl, *nAh, *nAl, *nBh, *nBl;
    int crow, ccol, ctz, nrow, ncol, ntz;
    decode(bid, cAh, cAl, cBh, cBl, crow, ccol, ctz);
    nAh = cAh; nAl = cAl; nBh = cBh; nBl = cBl; nrow = crow; ncol = ccol; ntz = ctz;
    if (mytiles > 1)
        decode(bid + nb, nAh, nAl, nBh, nBl, nrow, ncol, ntz);

    // ---- prologue: first two chunks of first tile (nch >= 4 always) ----
    issue(0, cAh, cAl, cBh, cBl, crow, ccol, 0);        CP_COMMIT();
    issue(1, cAh, cAl, cBh, cBl, crow, ccol, GBK);      CP_COMMIT();
    int si = 2;   // next issue stage
    int sc = 0;   // next compute stage

    for (int j = 0; j < mytiles; j++) {
#pragma unroll
        for (int mi = 0; mi < 4; mi++)
#pragma unroll
            for (int ni = 0; ni < 4; ni++)
#pragma unroll
                for (int q = 0; q < 4; q++) c[mi][ni][q] = 0.f;

        for (int kc = 0; kc < nch; kc++) {
            CP_WAIT1();
            __syncthreads();
            const int la = kc + 2;
            if (la < nch) {
                issue(si, cAh, cAl, cBh, cBl, crow, ccol, la * GBK);
                si = (si + 1 == NSTG) ? 0 : si + 1;
            } else if (j + 1 < mytiles) {
                issue(si, nAh, nAl, nBh, nBl, nrow, ncol, (la - nch) * GBK);
                si = (si + 1 == NSTG) ? 0 : si + 1;
            }
            CP_COMMIT();
            compute(sc);
            sc = (sc + 1 == NSTG) ? 0 : sc + 1;
        }

        // epilogue drains registers while next tile's chunks 0/1 are in flight
        epilogue(ctz, crow, ccol);

        cAh = nAh; cAl = nAl; cBh = nBh; cBl = nBl;
        crow = nrow; ccol = ncol; ctz = ntz;
        if (j + 2 < mytiles)
            decode(bid + (j + 2) * nb, nAh, nAl, nBh, nBl, nrow, ncol, ntz);
    }
}

// ===========================================================================
// ONE fused prep kernel: all transposes + concat splits, block-range dispatch.
// ===========================================================================
#define NB_WTK   512
#define NB_WTPK  768
#define NB_VT    16384
#define NB_CAT   24576
#define NB_PREP  (NB_WTK + NB_WTPK + NB_VT + NB_CAT)

__device__ __forceinline__ void transpose_tile(
    float (*tile)[33],
    const float* __restrict__ src, __nv_bfloat16* __restrict__ dh,
    __nv_bfloat16* __restrict__ dl, int R, int C, int tr, int tc)
{
    const int x = threadIdx.x & 31;
    const int y0 = threadIdx.x >> 5;       // 0..7
    const int r0 = tr * 32, c0 = tc * 32;
#pragma unroll
    for (int dy = 0; dy < 32; dy += 8)
        tile[y0 + dy][x] = src[(long long)(r0 + y0 + dy) * C + c0 + x];
    __syncthreads();
#pragma unroll
    for (int dy = 0; dy < 32; dy += 8) {
        const int c = c0 + y0 + dy;
        float v = tile[x][y0 + dy];
        __nv_bfloat16 h, l;
        split2(v, h, l);
        dh[(long long)c * R + r0 + x] = h;
        dl[(long long)c * R + r0 + x] = l;
    }
}

__global__ __launch_bounds__(256) void prep_kernel(
    const float* __restrict__ k1,  const float* __restrict__ pk1c,
    const float* __restrict__ k2,  const float* __restrict__ pk2c,
    const float* __restrict__ v1,  const float* __restrict__ v2,
    const float* __restrict__ W_k1, const float* __restrict__ W_k2,
    const float* __restrict__ W_pk1, const float* __restrict__ W_pk2)
{
    __shared__ float tile[32][33];
    const int b = blockIdx.x;
    const int tid = threadIdx.x;

    if (b < NB_WTK) {
        const int side = b >> 8;
        const int rem = b & 255;
        const int tr = rem >> 4, tc = rem & 15;
        transpose_tile(tile,
                       side ? W_k2 : W_k1,
                       side ? g_wtk2_h : g_wtk1_h,
                       side ? g_wtk2_l : g_wtk1_l,
                       KD, AD, tr, tc);
        return;
    }
    if (b < NB_WTK + NB_WTPK) {
        const int bb2 = b - NB_WTK;
        const int side = bb2 / 384;
        const int rem = bb2 - side * 384;
        const int tr = rem >> 4, tc = rem & 15;    // 24 x 16
        transpose_tile(tile,
                       side ? W_pk2 : W_pk1,
                       side ? g_wtpk2_h : g_wtpk1_h,
                       side ? g_wtpk2_l : g_wtpk1_l,
                       CATD, AD, tr, tc);
        return;
    }
    if (b < NB_WTK + NB_WTPK + NB_VT) {
        const int bb2 = b - (NB_WTK + NB_WTPK);
        const int z = bb2 >> 10;                   // 0..15
        const int rem = bb2 & 1023;
        const int tr = rem >> 4, tc = rem & 15;    // 64 x 16
        const bool second = z >= BB;
        const long long batch = second ? (z - BB) : z;
        const float* src = (second ? v2 : v1) + batch * (long long)SS * DV;
        __nv_bfloat16* dh = (second ? g_vt2_h : g_vt1_h) + batch * (long long)DV * SS;
        __nv_bfloat16* dl = (second ? g_vt2_l : g_vt1_l) + batch * (long long)DV * SS;
        transpose_tile(tile, src, dh, dl, SS, DV, tr, tc);
        return;
    }

    const int chunks = CATD / 4;                   // 192 per row
    const int Mtot = BB * SS;
    long long idx = (long long)(b - (NB_WTK + NB_WTPK + NB_VT)) * 256 + tid;
    const long long per_side = (long long)Mtot * chunks;
    const bool side2 = idx >= per_side;
    if (side2) idx -= per_side;
    const int r = (int)(idx / chunks);
    const int c = (int)(idx - (long long)r * chunks) * 4;

    const float* kk = side2 ? k2 : k1;
    const float* pp = side2 ? pk2c : pk1c;
    __nv_bfloat16* dh = side2 ? g_cat2_h : g_cat1_h;
    __nv_bfloat16* dl = side2 ? g_cat2_l : g_cat1_l;

    float4 v;
    if (c < KD) v = *(const float4*)(kk + (long long)r * KD + c);
    else        v = *(const float4*)(pp + (long long)r * PKD + (c - KD));

    __nv_bfloat16 h0, l0, h1, l1, h2, l2, h3, l3;
    split2(v.x, h0, l0); split2(v.y, h1, l1);
    split2(v.z, h2, l2); split2(v.w, h3, l3);
    long long base = (long long)r * CATD + c;
    *(uint2*)(dh + base) = make_uint2(pack_bf(h0, h1), pack_bf(h2, h3));
    *(uint2*)(dl + base) = make_uint2(pack_bf(l0, l1), pack_bf(l2, l3));
}

// ===========================================================================
// Masked in-place row softmax + fused bf16 split; both w matrices in one
// launch: blockIdx.y in [0,2*BB): y < BB -> w1 (lenR=l2,lenC=l1), else w2.
// ===========================================================================
__global__ __launch_bounds__(256) void softmax_mask_split_kernel(
    float* __restrict__ W1, float* __restrict__ W2,
    const int* __restrict__ l1, const int* __restrict__ l2)
{
    const int yraw = blockIdx.y;
    const bool second = yraw >= BB;
    const int b = second ? (yraw - BB) : yraw;
    float* W = second ? W2 : W1;
    __nv_bfloat16* Wh = second ? g_w2_h : g_w1_h;
    __nv_bfloat16* Wl = second ? g_w2_l : g_w1_l;
    const int* lenR = second ? l1 : l2;
    const int* lenC = second ? l2 : l1;

    const int r = blockIdx.x;
    const long long rowoff = ((long long)b * SS + r) * (long long)SS;
    float* row = W + rowoff;
    const int lc = read_len(lenC, b);
    const bool rover = r >= read_len(lenR, b);
    const int tid = threadIdx.x;
    const int c0 = tid * 8;

    float vals[8];
    float4 v0 = *(float4*)(row + c0);
    float4 v1 = *(float4*)(row + c0 + 4);
    vals[0] = v0.x; vals[1] = v0.y; vals[2] = v0.z; vals[3] = v0.w;
    vals[4] = v1.x; vals[5] = v1.y; vals[6] = v1.z; vals[7] = v1.w;

    float m = -CUDART_INF_F;
#pragma unroll
    for (int i = 0; i < 8; i++) {
        bool cover = (c0 + i) >= lc;
        if (cover != rover) vals[i] = -CUDART_INF_F;   // XOR mask semantics
        m = fmaxf(m, vals[i]);
    }

    const int lane = tid & 31, wrp = tid >> 5;
    __shared__ float smax[8];
    __shared__ float ssum[8];
#pragma unroll
    for (int o = 16; o; o >>= 1) m = fmaxf(m, __shfl_xor_sync(0xffffffffu, m, o));
    if (!lane) smax[wrp] = m;
    __syncthreads();
    m = smax[0];
#pragma unroll
    for (int i = 1; i < 8; i++) m = fmaxf(m, smax[i]);

    float s = 0.f;
#pragma unroll
    for (int i = 0; i < 8; i++) {
        vals[i] = __expf(vals[i] - m);
        s += vals[i];
    }
#pragma unroll
    for (int o = 16; o; o >>= 1) s += __shfl_xor_sync(0xffffffffu, s, o);
    if (!lane) ssum[wrp] = s;
    __syncthreads();
    s = ssum[0];
#pragma unroll
    for (int i = 1; i < 8; i++) s += ssum[i];
    const float inv = 1.f / s;

    uint32_t hiw[4], low[4];
#pragma unroll
    for (int i = 0; i < 8; i++) vals[i] *= inv;
#pragma unroll
    for (int j = 0; j < 4; j++) {
        __nv_bfloat16 h0, l0, h1, l1;
        split2(vals[2 * j + 0], h0, l0);
        split2(vals[2 * j + 1], h1, l1);
        hiw[j] = pack_bf(h0, h1);
        low[j] = pack_bf(l0, l1);
    }

    v0.x = vals[0]; v0.y = vals[1]; v0.z = vals[2]; v0.w = vals[3];
    v1.x = vals[4]; v1.y = vals[5]; v1.z = vals[6]; v1.w = vals[7];
    *(float4*)(row + c0) = v0;
    *(float4*)(row + c0 + 4) = v1;
    *(uint4*)(Wh + rowoff + c0) = make_uint4(hiw[0], hiw[1], hiw[2], hiw[3]);
    *(uint4*)(Wl + rowoff + c0) = make_uint4(low[0], low[1], low[2], low[3]);
}

// ===========================================================================
// Launch
// ===========================================================================
extern "C" void kernel_launch(void* const* d_in, const int* in_sizes, int n_in,
                              void* d_out, int out_size)
{
    const float* k1   = (const float*)d_in[0];
    const float* k2   = (const float*)d_in[1];
    const float* pk1c = (const float*)d_in[2];
    const float* pk2c = (const float*)d_in[3];
    const float* v1   = (const float*)d_in[4];
    const float* v2   = (const float*)d_in[5];
    const float* W_k1  = (const float*)d_in[6];
    const float* b_k1  = (const float*)d_in[7];
    const float* W_k2  = (const float*)d_in[8];
    const float* b_k2  = (const float*)d_in[9];
    const float* W_pk1 = (const float*)d_in[10];
    const float* b_pk1 = (const float*)d_in[11];
    const float* W_pk2 = (const float*)d_in[12];
    const float* b_pk2 = (const float*)d_in[13];
    const int* l1 = (const int*)d_in[14];
    const int* l2 = (const int*)d_in[15];

    float* o1 = (float*)d_out;                               // [B,S2,DV]
    float* o2 = o1 + (long long)BB * SS * DV;                // [B,S1,DV]
    float* w1 = o2 + (long long)BB * SS * DV;                // [B,S2,S1]
    float* w2 = w1 + (long long)BB * SS * SS;                // [B,S1,S2]

    __nv_bfloat16 *cat1h, *cat1l, *cat2h, *cat2l;
    __nv_bfloat16 *k1ph, *k1pl, *k2ph, *k2pl, *pk1h, *pk1l, *pk2h, *pk2l;
    __nv_bfloat16 *wtk1h, *wtk1l, *wtk2h, *wtk2l, *wtpk1h, *wtpk1l, *wtpk2h, *wtpk2l;
    __nv_bfloat16 *vt1h, *vt1l, *vt2h, *vt2l;
    __nv_bfloat16 *w1h, *w1l, *w2h, *w2l;
    cudaGetSymbolAddress((void**)&cat1h, g_cat1_h); cudaGetSymbolAddress((void**)&cat1l, g_cat1_l);
    cudaGetSymbolAddress((void**)&cat2h, g_cat2_h); cudaGetSymbolAddress((void**)&cat2l, g_cat2_l);
    cudaGetSymbolAddress((void**)&k1ph, g_k1p_h);   cudaGetSymbolAddress((void**)&k1pl, g_k1p_l);
    cudaGetSymbolAddress((void**)&k2ph, g_k2p_h);   cudaGetSymbolAddress((void**)&k2pl, g_k2p_l);
    cudaGetSymbolAddress((void**)&pk1h, g_pk1_h);   cudaGetSymbolAddress((void**)&pk1l, g_pk1_l);
    cudaGetSymbolAddress((void**)&pk2h, g_pk2_h);   cudaGetSymbolAddress((void**)&pk2l, g_pk2_l);
    cudaGetSymbolAddress((void**)&wtk1h, g_wtk1_h); cudaGetSymbolAddress((void**)&wtk1l, g_wtk1_l);
    cudaGetSymbolAddress((void**)&wtk2h, g_wtk2_h); cudaGetSymbolAddress((void**)&wtk2l, g_wtk2_l);
    cudaGetSymbolAddress((void**)&wtpk1h, g_wtpk1_h); cudaGetSymbolAddress((void**)&wtpk1l, g_wtpk1_l);
    cudaGetSymbolAddress((void**)&wtpk2h, g_wtpk2_h); cudaGetSymbolAddress((void**)&wtpk2l, g_wtpk2_l);
    cudaGetSymbolAddress((void**)&vt1h, g_vt1_h);   cudaGetSymbolAddress((void**)&vt1l, g_vt1_l);
    cudaGetSymbolAddress((void**)&vt2h, g_vt2_h);   cudaGetSymbolAddress((void**)&vt2l, g_vt2_l);
    cudaGetSymbolAddress((void**)&w1h, g_w1_h);     cudaGetSymbolAddress((void**)&w1l, g_w1_l);
    cudaGetSymbolAddress((void**)&w2h, g_w2_h);     cudaGetSymbolAddress((void**)&w2l, g_w2_l);

    cudaFuncSetAttribute(gemm_nt_mma,
                         cudaFuncAttributeMaxDynamicSharedMemorySize, SMEM_GEMM);

    static int nsm = 0;
    if (nsm == 0) {
        int dev = 0;
        cudaGetDevice(&dev);
        if (cudaDeviceGetAttribute(&nsm, cudaDevAttrMultiProcessorCount, dev)
                != cudaSuccess || nsm <= 0)
            nsm = 148;
    }

    const int Mtot = BB * SS;   // 16384

    // (1) ALL preprocessing in one launch
    prep_kernel<<<NB_PREP, 256>>>(k1, pk1c, k2, pk2c, v1, v2,
                                  W_k1, W_k2, W_pk1, W_pk2);

    // (2) k-projection GEMMs (persistent, z=2): k1p, k2p
    gemm_nt_mma<<<nsm, 256, SMEM_GEMM>>>(
        cat1h, cat1l, wtk1h, wtk1l, nullptr, k1ph, k1pl, b_k1,
        cat2h, cat2l, wtk2h, wtk2l, nullptr, k2ph, k2pl, b_k2,
        1, CATD, 0, KD, 0, KD, 0, AD, 1,
        AD / GBN, Mtot / GBM, (AD / GBN) * (Mtot / GBM) * 2);

    // (3) pk-projection GEMMs (persistent, z=2): pk1, pk2
    gemm_nt_mma<<<nsm, 256, SMEM_GEMM>>>(
        cat1h, cat1l, wtpk1h, wtpk1l, nullptr, pk1h, pk1l, b_pk1,
        cat2h, cat2l, wtpk2h, wtpk2l, nullptr, pk2h, pk2l, b_pk2,
        1, CATD, 0, CATD, 0, CATD, 0, AD, 1,
        AD / GBN, Mtot / GBM, (AD / GBN) * (Mtot / GBM) * 2);

    // (4) score GEMMs (persistent, z=16, fp32 into w regions)
    //     w1_pre[t,s] = pk2[t,:].k1p[s,:]   w2_pre[s,t] = pk1[s,:].k2p[t,:]
    gemm_nt_mma<<<nsm, 256, SMEM_GEMM>>>(
        pk2h, pk2l, k1ph, k1pl, w1, nullptr, nullptr, nullptr,
        pk1h, pk1l, k2ph, k2pl, w2, nullptr, nullptr, nullptr,
        BB, AD, (long long)SS * AD, AD, (long long)SS * AD,
        AD, (long long)SS * SS, SS, 0,
        SS / GBN, SS / GBM, (SS / GBN) * (SS / GBM) * 2 * BB);

    // (5) masked softmax + split, both w matrices (grid.y = 16)
    softmax_mask_split_kernel<<<dim3(SS, 2 * BB), 256>>>(w1, w2, l1, l2);

    // (6) output GEMMs (persistent, z=16): o1 = w1 @ v1, o2 = w2 @ v2
    gemm_nt_mma<<<nsm, 256, SMEM_GEMM>>>(
        w1h, w1l, vt1h, vt1l, o1, nullptr, nullptr, nullptr,
        w2h, w2l, vt2h, vt2l, o2, nullptr, nullptr, nullptr,
        BB, SS, (long long)SS * SS, SS, (long long)DV * SS,
        SS, (long long)SS * DV, DV, 0,
        DV / GBN, SS / GBM, (DV / GBN) * (SS / GBM) * 2 * BB);
}

// round 17
// speedup vs baseline: 1.7295x; 1.5780x over previous
#include <cuda_runtime.h>
#include <cuda_bf16.h>
#include <math_constants.h>
#include <cstdint>

// Problem dims
#define BB 8
#define SS 2048      // S1 == S2
#define KD 512       // K1_DIM == K2_DIM
#define PKD 256
#define CATD 768     // KD + PKD
#define AD 512       // ATT_DIM
#define DV 512

// ===========================================================================
// bf16 split scratch (static __device__ — allocation-free). 16B aligned.
// ===========================================================================
__device__ __align__(16) __nv_bfloat16 g_cat1_h[BB * SS * CATD];
__device__ __align__(16) __nv_bfloat16 g_cat1_l[BB * SS * CATD];
__device__ __align__(16) __nv_bfloat16 g_cat2_h[BB * SS * CATD];
__device__ __align__(16) __nv_bfloat16 g_cat2_l[BB * SS * CATD];

__device__ __align__(16) __nv_bfloat16 g_k1p_h[BB * SS * AD];
__device__ __align__(16) __nv_bfloat16 g_k1p_l[BB * SS * AD];
__device__ __align__(16) __nv_bfloat16 g_k2p_h[BB * SS * AD];
__device__ __align__(16) __nv_bfloat16 g_k2p_l[BB * SS * AD];
__device__ __align__(16) __nv_bfloat16 g_pk1_h[BB * SS * AD];
__device__ __align__(16) __nv_bfloat16 g_pk1_l[BB * SS * AD];
__device__ __align__(16) __nv_bfloat16 g_pk2_h[BB * SS * AD];
__device__ __align__(16) __nv_bfloat16 g_pk2_l[BB * SS * AD];

__device__ __align__(16) __nv_bfloat16 g_wtk1_h[AD * KD];
__device__ __align__(16) __nv_bfloat16 g_wtk1_l[AD * KD];
__device__ __align__(16) __nv_bfloat16 g_wtk2_h[AD * KD];
__device__ __align__(16) __nv_bfloat16 g_wtk2_l[AD * KD];
__device__ __align__(16) __nv_bfloat16 g_wtpk1_h[AD * CATD];
__device__ __align__(16) __nv_bfloat16 g_wtpk1_l[AD * CATD];
__device__ __align__(16) __nv_bfloat16 g_wtpk2_h[AD * CATD];
__device__ __align__(16) __nv_bfloat16 g_wtpk2_l[AD * CATD];

__device__ __align__(16) __nv_bfloat16 g_vt1_h[BB * DV * SS];
__device__ __align__(16) __nv_bfloat16 g_vt1_l[BB * DV * SS];
__device__ __align__(16) __nv_bfloat16 g_vt2_h[BB * DV * SS];
__device__ __align__(16) __nv_bfloat16 g_vt2_l[BB * DV * SS];

__device__ __align__(16) __nv_bfloat16 g_w1_h[BB * SS * SS];
__device__ __align__(16) __nv_bfloat16 g_w1_l[BB * SS * SS];
__device__ __align__(16) __nv_bfloat16 g_w2_h[BB * SS * SS];
__device__ __align__(16) __nv_bfloat16 g_w2_l[BB * SS * SS];

// ===========================================================================
// Helpers
// ===========================================================================
__device__ __forceinline__ uint32_t smem_u32(const void* p) {
    uint32_t a;
    asm("{ .reg .u64 t; cvta.to.shared.u64 t, %1; cvt.u32.u64 %0, t; }"
        : "=r"(a) : "l"(p));
    return a;
}

#define CP16(dst, src) \
    asm volatile("cp.async.cg.shared.global [%0], [%1], 16;" :: "r"(dst), "l"(src))
#define CP_COMMIT() asm volatile("cp.async.commit_group;" ::: "memory")
#define CP_WAIT1()  asm volatile("cp.async.wait_group 1;" ::: "memory")

#define LDSM_X4(r0, r1, r2, r3, addr) \
    asm volatile("ldmatrix.sync.aligned.m8n8.x4.shared.b16 {%0,%1,%2,%3}, [%4];" \
                 : "=r"(r0), "=r"(r1), "=r"(r2), "=r"(r3) : "r"(addr))

#define MMA16816(c, a, b0, b1) \
    asm volatile("mma.sync.aligned.m16n8k16.row.col.f32.bf16.bf16.f32 " \
                 "{%0,%1,%2,%3}, {%4,%5,%6,%7}, {%8,%9}, {%0,%1,%2,%3};" \
                 : "+f"((c)[0]), "+f"((c)[1]), "+f"((c)[2]), "+f"((c)[3]) \
                 : "r"((a)[0]), "r"((a)[1]), "r"((a)[2]), "r"((a)[3]), \
                   "r"(b0), "r"(b1))

__device__ __forceinline__ void split2(float x, __nv_bfloat16& h, __nv_bfloat16& l) {
    h = __float2bfloat16(x);
    l = __float2bfloat16(x - __bfloat162float(h));
}
__device__ __forceinline__ uint32_t pack_bf(__nv_bfloat16 a, __nv_bfloat16 b) {
    return ((uint32_t)__bfloat16_as_ushort(b) << 16) | (uint32_t)__bfloat16_as_ushort(a);
}

// Dtype-robust length read (lengths in [S/2,S); int64 LE view has arr[1]==0)
__device__ __forceinline__ int read_len(const int* __restrict__ arr, int b) {
    return (arr[1] == 0) ? arr[2 * b] : arr[b];
}

// ===========================================================================
// bf16x3-split NT GEMM on mma.sync (HMMA): C[m,n] = sum_k A[m,k]*B[n,k]
// GRID-PER-TILE (R10 structure restored). Two pointer-sets via blockIdx.z.
// 128x128 tile, BK=64, 3-stage cp.async pipeline, SW128-swizzled SMEM.
// R13b change: B-lo fragments get their OWN registers (bbl) and ALL 16
// LDSMs issue before the 48 MMAs — removes the WAR hazard that serialized
// the k16 body (B-lo LDSM had to wait for all 'lh' MMAs to retire).
// mode 0: write fp32 C.  mode 1: bias-add then write split bf16 (Ch, Cl).
// ===========================================================================
#define GBM 128
#define GBN 128
#define GBK 64
#define NSTG 3
#define TILE_B (128 * 128)            // 16 KB: 128 rows x 128 B (64 bf16)
#define STAGE_B (4 * TILE_B)          // Ah, Al, Bh, Bl
#define SMEM_GEMM (128 + NSTG * STAGE_B)

__global__ __launch_bounds__(256, 1) void gemm_nt_mma(
    const __nv_bfloat16* __restrict__ Ah0, const __nv_bfloat16* __restrict__ Al0,
    const __nv_bfloat16* __restrict__ Bh0, const __nv_bfloat16* __restrict__ Bl0,
    float* __restrict__ Cf0, __nv_bfloat16* __restrict__ Ch0,
    __nv_bfloat16* __restrict__ Cl0, const float* __restrict__ bias0,
    const __nv_bfloat16* __restrict__ Ah1, const __nv_bfloat16* __restrict__ Al1,
    const __nv_bfloat16* __restrict__ Bh1, const __nv_bfloat16* __restrict__ Bl1,
    float* __restrict__ Cf1, __nv_bfloat16* __restrict__ Ch1,
    __nv_bfloat16* __restrict__ Cl1, const float* __restrict__ bias1,
    int zsplit,
    int ldA, long long bsA, int ldB, long long bsB,
    int Kred, long long bsC, int ldC, int mode)
{
    extern __shared__ char smem_raw[];
    uint32_t sb0 = smem_u32(smem_raw);
    uint32_t sbase = (sb0 + 127u) & ~127u;
    char* stages = smem_raw + (sbase - sb0);

    const int tid = threadIdx.x;
    const int lane = tid & 31;
    const int wid = tid >> 5;
    const int wm = wid & 1;            // 2 m-subtiles of 64
    const int wn = wid >> 1;           // 4 n-subtiles of 32

    const int zraw = blockIdx.z;
    const bool second = zraw >= zsplit;
    const long long bz = second ? (zraw - zsplit) : zraw;
    const __nv_bfloat16* Ah = second ? Ah1 : Ah0;
    const __nv_bfloat16* Al = second ? Al1 : Al0;
    const __nv_bfloat16* Bh = second ? Bh1 : Bh0;
    const __nv_bfloat16* Bl = second ? Bl1 : Bl0;
    float* Cf = second ? Cf1 : Cf0;
    __nv_bfloat16* Ch = second ? Ch1 : Ch0;
    __nv_bfloat16* Cl = second ? Cl1 : Cl0;
    const float* bias = second ? bias1 : bias0;

    const int row0 = blockIdx.y * GBM;
    const int col0 = blockIdx.x * GBN;
    Ah += bz * bsA; Al += bz * bsA;
    Bh += bz * bsB; Bl += bz * bsB;

    float c[4][4][4];
#pragma unroll
    for (int mi = 0; mi < 4; mi++)
#pragma unroll
        for (int ni = 0; ni < 4; ni++)
#pragma unroll
            for (int q = 0; q < 4; q++) c[mi][ni][q] = 0.f;

    const int nch = Kred / GBK;

    const int rr = tid >> 3;           // 0..31
    const int cc = tid & 7;            // 16B chunk within 128B row

    auto issue = [&](int ic) {
        char* st = stages + (ic % NSTG) * STAGE_B;
        const int k0 = ic * GBK;
#pragma unroll
        for (int p = 0; p < 4; p++) {
            const int row = rr + p * 32;
            const int sw = row * 128 + ((cc ^ (row & 7)) << 4);
            const uint32_t da = smem_u32(st + sw);
            const long long ka = (long long)(row0 + row) * ldA + k0 + cc * 8;
            const long long kb = (long long)(col0 + row) * ldB + k0 + cc * 8;
            CP16(da,                Ah + ka);
            CP16(da + TILE_B,       Al + ka);
            CP16(da + 2 * TILE_B,   Bh + kb);
            CP16(da + 3 * TILE_B,   Bl + kb);
        }
    };

    const int a_r  = lane & 15;
    const int a_k2 = lane >> 4;
    const int b_r  = ((lane >> 4) << 3) + (lane & 7);
    const int b_k2 = (lane >> 3) & 1;

    auto compute = [&](int ic) {
        const uint32_t stu = smem_u32(stages + (ic % NSTG) * STAGE_B);
#pragma unroll
        for (int k16 = 0; k16 < GBK / 16; k16++) {
            uint32_t ah[4][4], al[4][4], bbh[4][2], bbl[4][2];
            // ALL fragment loads first (16 LDSM), no WAR hazards
#pragma unroll
            for (int mi = 0; mi < 4; mi++) {
                const int row = wm * 64 + mi * 16 + a_r;
                const int kch = k16 * 2 + a_k2;
                const uint32_t off = row * 128 + ((kch ^ (row & 7)) << 4);
                LDSM_X4(ah[mi][0], ah[mi][1], ah[mi][2], ah[mi][3], stu + off);
                LDSM_X4(al[mi][0], al[mi][1], al[mi][2], al[mi][3],
                        stu + TILE_B + off);
            }
#pragma unroll
            for (int pi = 0; pi < 2; pi++) {
                const int n = wn * 32 + pi * 16 + b_r;
                const int kch = k16 * 2 + b_k2;
                const uint32_t off = n * 128 + ((kch ^ (n & 7)) << 4);
                uint32_t t0, t1, t2, t3;
                LDSM_X4(t0, t1, t2, t3, stu + 2 * TILE_B + off);
                bbh[2 * pi][0] = t0;     bbh[2 * pi][1] = t1;
                bbh[2 * pi + 1][0] = t2; bbh[2 * pi + 1][1] = t3;
                uint32_t u0, u1, u2, u3;
                LDSM_X4(u0, u1, u2, u3, stu + 3 * TILE_B + off);
                bbl[2 * pi][0] = u0;     bbl[2 * pi][1] = u1;
                bbl[2 * pi + 1][0] = u2; bbl[2 * pi + 1][1] = u3;
            }
            // 48 MMAs back-to-back: hh, lh, hl
#pragma unroll
            for (int mi = 0; mi < 4; mi++)
#pragma unroll
                for (int ni = 0; ni < 4; ni++)
                    MMA16816(c[mi][ni], ah[mi], bbh[ni][0], bbh[ni][1]);
#pragma unroll
            for (int mi = 0; mi < 4; mi++)
#pragma unroll
                for (int ni = 0; ni < 4; ni++)
                    MMA16816(c[mi][ni], al[mi], bbh[ni][0], bbh[ni][1]);
#pragma unroll
            for (int mi = 0; mi < 4; mi++)
#pragma unroll
                for (int ni = 0; ni < 4; ni++)
                    MMA16816(c[mi][ni], ah[mi], bbl[ni][0], bbl[ni][1]);
        }
    };

    issue(0); CP_COMMIT();
    issue(1); CP_COMMIT();
    for (int i = 0; i < nch; i++) {
        CP_WAIT1();
        __syncthreads();
        if (i + 2 < nch) issue(i + 2);
        CP_COMMIT();
        compute(i);
    }

    const int rr4 = lane >> 2;
    const int cc2 = (lane & 3) * 2;
    const int r_base = row0 + wm * 64;
    const int c_base = col0 + wn * 32;

    if (mode == 0) {
        float* out = Cf + bz * bsC;
#pragma unroll
        for (int mi = 0; mi < 4; mi++)
#pragma unroll
            for (int ni = 0; ni < 4; ni++) {
                const int r = r_base + mi * 16 + rr4;
                const int col = c_base + ni * 8 + cc2;
                *(float2*)(out + (long long)r * ldC + col) =
                    make_float2(c[mi][ni][0], c[mi][ni][1]);
                *(float2*)(out + (long long)(r + 8) * ldC + col) =
                    make_float2(c[mi][ni][2], c[mi][ni][3]);
            }
    } else {
#pragma unroll
        for (int mi = 0; mi < 4; mi++)
#pragma unroll
            for (int ni = 0; ni < 4; ni++) {
                const int r = r_base + mi * 16 + rr4;
                const int col = c_base + ni * 8 + cc2;
                const float bx = bias[col], by = bias[col + 1];
                float x0 = c[mi][ni][0] + bx, x1 = c[mi][ni][1] + by;
                float x2 = c[mi][ni][2] + bx, x3 = c[mi][ni][3] + by;
                __nv_bfloat16 h0, l0, h1, l1;
                split2(x0, h0, l0); split2(x1, h1, l1);
                *(uint32_t*)(Ch + (long long)r * ldC + col) = pack_bf(h0, h1);
                *(uint32_t*)(Cl + (long long)r * ldC + col) = pack_bf(l0, l1);
                split2(x2, h0, l0); split2(x3, h1, l1);
                *(uint32_t*)(Ch + (long long)(r + 8) * ldC + col) = pack_bf(h0, h1);
                *(uint32_t*)(Cl + (long long)(r + 8) * ldC + col) = pack_bf(l0, l1);
            }
    }
}

// ===========================================================================
// ONE fused prep kernel: all transposes + concat splits, block-range dispatch.
// ===========================================================================
#define NB_WTK   512
#define NB_WTPK  768
#define NB_VT    16384
#define NB_CAT   24576
#define NB_PREP  (NB_WTK + NB_WTPK + NB_VT + NB_CAT)

__device__ __forceinline__ void transpose_tile(
    float (*tile)[33],
    const float* __restrict__ src, __nv_bfloat16* __restrict__ dh,
    __nv_bfloat16* __restrict__ dl, int R, int C, int tr, int tc)
{
    const int x = threadIdx.x & 31;
    const int y0 = threadIdx.x >> 5;       // 0..7
    const int r0 = tr * 32, c0 = tc * 32;
#pragma unroll
    for (int dy = 0; dy < 32; dy += 8)
        tile[y0 + dy][x] = src[(long long)(r0 + y0 + dy) * C + c0 + x];
    __syncthreads();
#pragma unroll
    for (int dy = 0; dy < 32; dy += 8) {
        const int c = c0 + y0 + dy;
        float v = tile[x][y0 + dy];
        __nv_bfloat16 h, l;
        split2(v, h, l);
        dh[(long long)c * R + r0 + x] = h;
        dl[(long long)c * R + r0 + x] = l;
    }
}

__global__ __launch_bounds__(256) void prep_kernel(
    const float* __restrict__ k1,  const float* __restrict__ pk1c,
    const float* __restrict__ k2,  const float* __restrict__ pk2c,
    const float* __restrict__ v1,  const float* __restrict__ v2,
    const float* __restrict__ W_k1, const float* __restrict__ W_k2,
    const float* __restrict__ W_pk1, const float* __restrict__ W_pk2)
{
    __shared__ float tile[32][33];
    const int b = blockIdx.x;
    const int tid = threadIdx.x;

    if (b < NB_WTK) {
        const int side = b >> 8;
        const int rem = b & 255;
        const int tr = rem >> 4, tc = rem & 15;
        transpose_tile(tile,
                       side ? W_k2 : W_k1,
                       side ? g_wtk2_h : g_wtk1_h,
                       side ? g_wtk2_l : g_wtk1_l,
                       KD, AD, tr, tc);
        return;
    }
    if (b < NB_WTK + NB_WTPK) {
        const int bb2 = b - NB_WTK;
        const int side = bb2 / 384;
        const int rem = bb2 - side * 384;
        const int tr = rem >> 4, tc = rem & 15;    // 24 x 16
        transpose_tile(tile,
                       side ? W_pk2 : W_pk1,
                       side ? g_wtpk2_h : g_wtpk1_h,
                       side ? g_wtpk2_l : g_wtpk1_l,
                       CATD, AD, tr, tc);
        return;
    }
    if (b < NB_WTK + NB_WTPK + NB_VT) {
        const int bb2 = b - (NB_WTK + NB_WTPK);
        const int z = bb2 >> 10;                   // 0..15
        const int rem = bb2 & 1023;
        const int tr = rem >> 4, tc = rem & 15;    // 64 x 16
        const bool second = z >= BB;
        const long long batch = second ? (z - BB) : z;
        const float* src = (second ? v2 : v1) + batch * (long long)SS * DV;
        __nv_bfloat16* dh = (second ? g_vt2_h : g_vt1_h) + batch * (long long)DV * SS;
        __nv_bfloat16* dl = (second ? g_vt2_l : g_vt1_l) + batch * (long long)DV * SS;
        transpose_tile(tile, src, dh, dl, SS, DV, tr, tc);
        return;
    }

    const int chunks = CATD / 4;                   // 192 per row
    const int Mtot = BB * SS;
    long long idx = (long long)(b - (NB_WTK + NB_WTPK + NB_VT)) * 256 + tid;
    const long long per_side = (long long)Mtot * chunks;
    const bool side2 = idx >= per_side;
    if (side2) idx -= per_side;
    const int r = (int)(idx / chunks);
    const int c = (int)(idx - (long long)r * chunks) * 4;

    const float* kk = side2 ? k2 : k1;
    const float* pp = side2 ? pk2c : pk1c;
    __nv_bfloat16* dh = side2 ? g_cat2_h : g_cat1_h;
    __nv_bfloat16* dl = side2 ? g_cat2_l : g_cat1_l;

    float4 v;
    if (c < KD) v = *(const float4*)(kk + (long long)r * KD + c);
    else        v = *(const float4*)(pp + (long long)r * PKD + (c - KD));

    __nv_bfloat16 h0, l0, h1, l1, h2, l2, h3, l3;
    split2(v.x, h0, l0); split2(v.y, h1, l1);
    split2(v.z, h2, l2); split2(v.w, h3, l3);
    long long base = (long long)r * CATD + c;
    *(uint2*)(dh + base) = make_uint2(pack_bf(h0, h1), pack_bf(h2, h3));
    *(uint2*)(dl + base) = make_uint2(pack_bf(l0, l1), pack_bf(l2, l3));
}

// ===========================================================================
// Masked in-place row softmax + fused bf16 split; both w matrices in one
// launch: blockIdx.y in [0,2*BB): y < BB -> w1 (lenR=l2,lenC=l1), else w2.
// ===========================================================================
__global__ __launch_bounds__(256) void softmax_mask_split_kernel(
    float* __restrict__ W1, float* __restrict__ W2,
    const int* __restrict__ l1, const int* __restrict__ l2)
{
    const int yraw = blockIdx.y;
    const bool second = yraw >= BB;
    const int b = second ? (yraw - BB) : yraw;
    float* W = second ? W2 : W1;
    __nv_bfloat16* Wh = second ? g_w2_h : g_w1_h;
    __nv_bfloat16* Wl = second ? g_w2_l : g_w1_l;
    const int* lenR = second ? l1 : l2;
    const int* lenC = second ? l2 : l1;

    const int r = blockIdx.x;
    const long long rowoff = ((long long)b * SS + r) * (long long)SS;
    float* row = W + rowoff;
    const int lc = read_len(lenC, b);
    const bool rover = r >= read_len(lenR, b);
    const int tid = threadIdx.x;
    const int c0 = tid * 8;

    float vals[8];
    float4 v0 = *(float4*)(row + c0);
    float4 v1 = *(float4*)(row + c0 + 4);
    vals[0] = v0.x; vals[1] = v0.y; vals[2] = v0.z; vals[3] = v0.w;
    vals[4] = v1.x; vals[5] = v1.y; vals[6] = v1.z; vals[7] = v1.w;

    float m = -CUDART_INF_F;
#pragma unroll
    for (int i = 0; i < 8; i++) {
        bool cover = (c0 + i) >= lc;
        if (cover != rover) vals[i] = -CUDART_INF_F;   // XOR mask semantics
        m = fmaxf(m, vals[i]);
    }

    const int lane = tid & 31, wrp = tid >> 5;
    __shared__ float smax[8];
    __shared__ float ssum[8];
#pragma unroll
    for (int o = 16; o; o >>= 1) m = fmaxf(m, __shfl_xor_sync(0xffffffffu, m, o));
    if (!lane) smax[wrp] = m;
    __syncthreads();
    m = smax[0];
#pragma unroll
    for (int i = 1; i < 8; i++) m = fmaxf(m, smax[i]);

    float s = 0.f;
#pragma unroll
    for (int i = 0; i < 8; i++) {
        vals[i] = __expf(vals[i] - m);
        s += vals[i];
    }
#pragma unroll
    for (int o = 16; o; o >>= 1) s += __shfl_xor_sync(0xffffffffu, s, o);
    if (!lane) ssum[wrp] = s;
    __syncthreads();
    s = ssum[0];
#pragma unroll
    for (int i = 1; i < 8; i++) s += ssum[i];
    const float inv = 1.f / s;

    uint32_t hiw[4], low[4];
#pragma unroll
    for (int i = 0; i < 8; i++) vals[i] *= inv;
#pragma unroll
    for (int j = 0; j < 4; j++) {
        __nv_bfloat16 h0, l0, h1, l1;
        split2(vals[2 * j + 0], h0, l0);
        split2(vals[2 * j + 1], h1, l1);
        hiw[j] = pack_bf(h0, h1);
        low[j] = pack_bf(l0, l1);
    }

    v0.x = vals[0]; v0.y = vals[1]; v0.z = vals[2]; v0.w = vals[3];
    v1.x = vals[4]; v1.y = vals[5]; v1.z = vals[6]; v1.w = vals[7];
    *(float4*)(row + c0) = v0;
    *(float4*)(row + c0 + 4) = v1;
    *(uint4*)(Wh + rowoff + c0) = make_uint4(hiw[0], hiw[1], hiw[2], hiw[3]);
    *(uint4*)(Wl + rowoff + c0) = make_uint4(low[0], low[1], low[2], low[3]);
}

// ===========================================================================
// Launch
// ===========================================================================
extern "C" void kernel_launch(void* const* d_in, const int* in_sizes, int n_in,
                              void* d_out, int out_size)
{
    const float* k1   = (const float*)d_in[0];
    const float* k2   = (const float*)d_in[1];
    const float* pk1c = (const float*)d_in[2];
    const float* pk2c = (const float*)d_in[3];
    const float* v1   = (const float*)d_in[4];
    const float* v2   = (const float*)d_in[5];
    const float* W_k1  = (const float*)d_in[6];
    const float* b_k1  = (const float*)d_in[7];
    const float* W_k2  = (const float*)d_in[8];
    const float* b_k2  = (const float*)d_in[9];
    const float* W_pk1 = (const float*)d_in[10];
    const float* b_pk1 = (const float*)d_in[11];
    const float* W_pk2 = (const float*)d_in[12];
    const float* b_pk2 = (const float*)d_in[13];
    const int* l1 = (const int*)d_in[14];
    const int* l2 = (const int*)d_in[15];

    float* o1 = (float*)d_out;                               // [B,S2,DV]
    float* o2 = o1 + (long long)BB * SS * DV;                // [B,S1,DV]
    float* w1 = o2 + (long long)BB * SS * DV;                // [B,S2,S1]
    float* w2 = w1 + (long long)BB * SS * SS;                // [B,S1,S2]

    __nv_bfloat16 *cat1h, *cat1l, *cat2h, *cat2l;
    __nv_bfloat16 *k1ph, *k1pl, *k2ph, *k2pl, *pk1h, *pk1l, *pk2h, *pk2l;
    __nv_bfloat16 *wtk1h, *wtk1l, *wtk2h, *wtk2l, *wtpk1h, *wtpk1l, *wtpk2h, *wtpk2l;
    __nv_bfloat16 *vt1h, *vt1l, *vt2h, *vt2l;
    __nv_bfloat16 *w1h, *w1l, *w2h, *w2l;
    cudaGetSymbolAddress((void**)&cat1h, g_cat1_h); cudaGetSymbolAddress((void**)&cat1l, g_cat1_l);
    cudaGetSymbolAddress((void**)&cat2h, g_cat2_h); cudaGetSymbolAddress((void**)&cat2l, g_cat2_l);
    cudaGetSymbolAddress((void**)&k1ph, g_k1p_h);   cudaGetSymbolAddress((void**)&k1pl, g_k1p_l);
    cudaGetSymbolAddress((void**)&k2ph, g_k2p_h);   cudaGetSymbolAddress((void**)&k2pl, g_k2p_l);
    cudaGetSymbolAddress((void**)&pk1h, g_pk1_h);   cudaGetSymbolAddress((void**)&pk1l, g_pk1_l);
    cudaGetSymbolAddress((void**)&pk2h, g_pk2_h);   cudaGetSymbolAddress((void**)&pk2l, g_pk2_l);
    cudaGetSymbolAddress((void**)&wtk1h, g_wtk1_h); cudaGetSymbolAddress((void**)&wtk1l, g_wtk1_l);
    cudaGetSymbolAddress((void**)&wtk2h, g_wtk2_h); cudaGetSymbolAddress((void**)&wtk2l, g_wtk2_l);
    cudaGetSymbolAddress((void**)&wtpk1h, g_wtpk1_h); cudaGetSymbolAddress((void**)&wtpk1l, g_wtpk1_l);
    cudaGetSymbolAddress((void**)&wtpk2h, g_wtpk2_h); cudaGetSymbolAddress((void**)&wtpk2l, g_wtpk2_l);
    cudaGetSymbolAddress((void**)&vt1h, g_vt1_h);   cudaGetSymbolAddress((void**)&vt1l, g_vt1_l);
    cudaGetSymbolAddress((void**)&vt2h, g_vt2_h);   cudaGetSymbolAddress((void**)&vt2l, g_vt2_l);
    cudaGetSymbolAddress((void**)&w1h, g_w1_h);     cudaGetSymbolAddress((void**)&w1l, g_w1_l);
    cudaGetSymbolAddress((void**)&w2h, g_w2_h);     cudaGetSymbolAddress((void**)&w2l, g_w2_l);

    cudaFuncSetAttribute(gemm_nt_mma,
                         cudaFuncAttributeMaxDynamicSharedMemorySize, SMEM_GEMM);

    const int Mtot = BB * SS;   // 16384

    // (1) ALL preprocessing in one launch
    prep_kernel<<<NB_PREP, 256>>>(k1, pk1c, k2, pk2c, v1, v2,
                                  W_k1, W_k2, W_pk1, W_pk2);

    // (2) k-projection GEMMs merged (z=2): k1p, k2p
    gemm_nt_mma<<<dim3(AD / GBN, Mtot / GBM, 2), 256, SMEM_GEMM>>>(
        cat1h, cat1l, wtk1h, wtk1l, nullptr, k1ph, k1pl, b_k1,
        cat2h, cat2l, wtk2h, wtk2l, nullptr, k2ph, k2pl, b_k2,
        1, CATD, 0, KD, 0, KD, 0, AD, 1);
    // (3) pk-projection GEMMs merged (z=2): pk1, pk2
    gemm_nt_mma<<<dim3(AD / GBN, Mtot / GBM, 2), 256, SMEM_GEMM>>>(
        cat1h, cat1l, wtpk1h, wtpk1l, nullptr, pk1h, pk1l, b_pk1,
        cat2h, cat2l, wtpk2h, wtpk2l, nullptr, pk2h, pk2l, b_pk2,
        1, CATD, 0, CATD, 0, CATD, 0, AD, 1);

    // (4) score GEMMs merged (z=16, fp32 into w regions)
    //     w1_pre[t,s] = pk2[t,:].k1p[s,:]   w2_pre[s,t] = pk1[s,:].k2p[t,:]
    gemm_nt_mma<<<dim3(SS / GBN, SS / GBM, 2 * BB), 256, SMEM_GEMM>>>(
        pk2h, pk2l, k1ph, k1pl, w1, nullptr, nullptr, nullptr,
        pk1h, pk1l, k2ph, k2pl, w2, nullptr, nullptr, nullptr,
        BB, AD, (long long)SS * AD, AD, (long long)SS * AD,
        AD, (long long)SS * SS, SS, 0);

    // (5) masked softmax + split, both w matrices (grid.y = 16)
    softmax_mask_split_kernel<<<dim3(SS, 2 * BB), 256>>>(w1, w2, l1, l2);

    // (6) output GEMMs merged (z=16): o1 = w1 @ v1, o2 = w2 @ v2
    gemm_nt_mma<<<dim3(DV / GBN, SS / GBM, 2 * BB), 256, SMEM_GEMM>>>(
        w1h, w1l, vt1h, vt1l, o1, nullptr, nullptr, nullptr,
        w2h, w2l, vt2h, vt2l, o2, nullptr, nullptr, nullptr,
        BB, SS, (long long)SS * SS, SS, (long long)DV * SS,
        SS, (long long)SS * DV, DV, 0);
}